// round 1
// baseline (speedup 1.0000x reference)
#include <cuda_runtime.h>
#include <cstdint>
#include <cstddef>

// Problem constants
#define B_    32
#define S_    577          // 24*24 + 1
#define E_    768
#define H_    12
#define DH_   64
#define PT_   24
#define QKV3_ 2304         // 3*E
#define NROT_ 576          // S-1 rope positions

// Scratch (device globals; allocation-free per harness rules)
__device__ float g_qkv[(size_t)B_ * S_ * QKV3_];   // [b*s, 3*H*Dh] with (i3,h,d) col order
__device__ float g_ctx[(size_t)B_ * S_ * E_];      // [b*s, h*Dh]
__device__ float g_cos[NROT_ * DH_];
__device__ float g_sin[NROT_ * DH_];

// ---------------------------------------------------------------------------
// RoPE table: 2D rope, dim = Dh/2 = 32 per axis, 16 freqs each, repeat(2)
// ---------------------------------------------------------------------------
__global__ void rope_build_kernel() {
    int p = blockIdx.x;      // 0..575
    int d = threadIdx.x;     // 0..63
    int r = p / PT_, c = p % PT_;
    int tcoord = (d < 32) ? r : c;
    int dd = (d < 32) ? d : d - 32;
    int fi = dd >> 1;        // freq index 0..15
    float inv = powf(10000.0f, -(float)(2 * fi) / 32.0f);
    float ang = (float)tcoord * inv;
    g_cos[p * DH_ + d] = cosf(ang);
    g_sin[p * DH_ + d] = sinf(ang);
}

// ---------------------------------------------------------------------------
// Generic tiled fp32 GEMM with bias:  C[M,N] = A[M,K] @ B[K,N] + bias[N]
// 64x64 tile, BK=16, 256 threads, 4x4 per thread.
// ---------------------------------------------------------------------------
#define BM 64
#define BN 64
#define BK 16

__global__ void gemm_bias_kernel(const float* __restrict__ A,
                                 const float* __restrict__ Bm,
                                 const float* __restrict__ bias,
                                 float* __restrict__ C,
                                 int M, int N, int K) {
    __shared__ float As[BM][BK];
    __shared__ float Bs[BK][BN];
    int tid = threadIdx.x;
    int tx = tid & 15, ty = tid >> 4;
    int row0 = blockIdx.y * BM;
    int col0 = blockIdx.x * BN;

    float acc[4][4] = {};

    for (int k0 = 0; k0 < K; k0 += BK) {
        #pragma unroll
        for (int i = 0; i < 4; i++) {
            int idx = tid + i * 256;
            int r = idx >> 4, c = idx & 15;
            int gr = row0 + r;
            As[r][c] = (gr < M) ? A[(size_t)gr * K + k0 + c] : 0.0f;
        }
        #pragma unroll
        for (int i = 0; i < 4; i++) {
            int idx = tid + i * 256;
            int r = idx >> 6, c = idx & 63;
            Bs[r][c] = Bm[(size_t)(k0 + r) * N + col0 + c];
        }
        __syncthreads();
        #pragma unroll
        for (int kk = 0; kk < BK; kk++) {
            float a[4], b[4];
            #pragma unroll
            for (int i = 0; i < 4; i++) a[i] = As[ty * 4 + i][kk];
            #pragma unroll
            for (int j = 0; j < 4; j++) b[j] = Bs[kk][tx * 4 + j];
            #pragma unroll
            for (int i = 0; i < 4; i++)
                #pragma unroll
                for (int j = 0; j < 4; j++)
                    acc[i][j] += a[i] * b[j];
        }
        __syncthreads();
    }

    #pragma unroll
    for (int i = 0; i < 4; i++) {
        int gr = row0 + ty * 4 + i;
        if (gr >= M) continue;
        #pragma unroll
        for (int j = 0; j < 4; j++) {
            int gc = col0 + tx * 4 + j;
            C[(size_t)gr * N + gc] = acc[i][j] + bias[gc];
        }
    }
}

// ---------------------------------------------------------------------------
// In-place RoPE on q and k parts of g_qkv. grid = B*(S-1), block = 768.
// thread t = h*64 + d
// ---------------------------------------------------------------------------
__global__ void rope_apply_kernel(float* __restrict__ qkv) {
    int bs = blockIdx.x;
    int b = bs / NROT_;
    int p = bs % NROT_;          // rope position
    int s = p + 1;               // seq index (s=0 is NO_ROPE passthrough)
    int t = threadIdx.x;         // 0..767
    int d = t & 63;

    float cs = g_cos[p * DH_ + d];
    float sn = g_sin[p * DH_ + d];

    size_t base = (size_t)(b * S_ + s) * QKV3_;
    int partner = t ^ 1;

    float qv = qkv[base + t];
    float kv = qkv[base + E_ + t];
    float qp = qkv[base + partner];
    float kp = qkv[base + E_ + partner];
    __syncthreads();

    float sgn = (d & 1) ? 1.0f : -1.0f;
    qkv[base + t]      = qv * cs + sgn * qp * sn;
    qkv[base + E_ + t] = kv * cs + sgn * kp * sn;
}

// ---------------------------------------------------------------------------
// Attention: one block per (b, h, q). 128 threads.
// scores row in smem, softmax, then P@V with 2-way k-split.
// ---------------------------------------------------------------------------
__global__ void attn_kernel(const float* __restrict__ qkv,
                            const unsigned char* __restrict__ mask,
                            float* __restrict__ ctx) {
    int idx = blockIdx.x;
    int qi = idx % S_;
    int bh = idx / S_;
    int h = bh % H_;
    int b = bh / H_;

    __shared__ float sq[DH_];
    __shared__ float sc[S_];
    __shared__ float red[128];

    int tid = threadIdx.x;
    size_t qrow = (size_t)(b * S_ + qi) * QKV3_;
    if (tid < DH_) sq[tid] = qkv[qrow + h * DH_ + tid];
    __syncthreads();

    const size_t koff = (size_t)E_ + h * DH_;
    float lmax = -3.4e38f;
    for (int k = tid; k < S_; k += 128) {
        const float* kr = qkv + (size_t)(b * S_ + k) * QKV3_ + koff;
        float dot = 0.0f;
        #pragma unroll
        for (int d = 0; d < DH_; d++) dot += sq[d] * kr[d];
        dot *= 0.125f;   // 1/sqrt(64)
        if (mask[b * S_ + k]) dot = -3.4028235e38f;
        sc[k] = dot;
        lmax = fmaxf(lmax, dot);
    }
    red[tid] = lmax;
    __syncthreads();
    #pragma unroll
    for (int o = 64; o > 0; o >>= 1) {
        if (tid < o) red[tid] = fmaxf(red[tid], red[tid + o]);
        __syncthreads();
    }
    float m = red[0];
    __syncthreads();

    float lsum = 0.0f;
    for (int k = tid; k < S_; k += 128) {
        float e = expf(sc[k] - m);
        sc[k] = e;
        lsum += e;
    }
    red[tid] = lsum;
    __syncthreads();
    #pragma unroll
    for (int o = 64; o > 0; o >>= 1) {
        if (tid < o) red[tid] += red[tid + o];
        __syncthreads();
    }
    float inv = 1.0f / red[0];
    __syncthreads();

    // P @ V : 2 groups of 64 threads split the k range
    int g = tid >> 6;
    int d = tid & 63;
    const float* vcol = qkv + (size_t)(b * S_) * QKV3_ + 2 * E_ + h * DH_ + d;
    float acc = 0.0f;
    for (int k = g; k < S_; k += 2) acc += sc[k] * vcol[(size_t)k * QKV3_];
    red[tid] = acc;
    __syncthreads();
    if (tid < DH_) {
        ctx[(size_t)(b * S_ + qi) * E_ + h * DH_ + tid] =
            (red[tid] + red[tid + 64]) * inv;
    }
}

// ---------------------------------------------------------------------------
// Launch
// ---------------------------------------------------------------------------
extern "C" void kernel_launch(void* const* d_in, const int* in_sizes, int n_in,
                              void* d_out, int out_size) {
    const float* x      = (const float*)d_in[0];
    const unsigned char* mask = (const unsigned char*)d_in[1];
    const float* W_qkv  = (const float*)d_in[2];
    const float* b_qkv  = (const float*)d_in[3];
    const float* W_proj = (const float*)d_in[4];
    const float* b_proj = (const float*)d_in[5];
    float* out = (float*)d_out;

    float* qkv; cudaGetSymbolAddress((void**)&qkv, g_qkv);
    float* ctx; cudaGetSymbolAddress((void**)&ctx, g_ctx);

    const int M = B_ * S_;   // 18464

    // 1) rope tables
    rope_build_kernel<<<NROT_, DH_>>>();

    // 2) qkv = x @ W_qkv + b_qkv   (M x 768 @ 768 x 2304)
    {
        dim3 grid(QKV3_ / BN, (M + BM - 1) / BM);
        gemm_bias_kernel<<<grid, 256>>>(x, W_qkv, b_qkv, qkv, M, QKV3_, E_);
    }

    // 3) rope on q,k (positions 1..576)
    rope_apply_kernel<<<B_ * NROT_, E_>>>(qkv);

    // 4) attention
    attn_kernel<<<B_ * H_ * S_, 128>>>(qkv, mask, ctx);

    // 5) out = ctx @ W_proj + b_proj
    {
        dim3 grid(E_ / BN, (M + BM - 1) / BM);
        gemm_bias_kernel<<<grid, 256>>>(ctx, W_proj, b_proj, out, M, E_, E_);
    }
}

// round 3
// speedup vs baseline: 8.0406x; 8.0406x over previous
#include <cuda_runtime.h>
#include <cstdint>
#include <cstddef>

// Problem constants
#define B_    32
#define S_    577          // 24*24 + 1
#define E_    768
#define H_    12
#define DH_   64
#define PT_   24
#define QKV3_ 2304         // 3*E
#define NROT_ 576          // S-1 rope positions
#define BH_   (B_ * H_)    // 384

// Scratch (device globals; allocation-free per harness rules)
__device__ float g_qkv[(size_t)B_ * S_ * QKV3_];   // [b*s, (q|k|v) x h x d]
__device__ float g_ctx[(size_t)B_ * S_ * E_];      // [b*s, h*d]
__device__ float g_q[(size_t)BH_ * S_ * DH_];      // [b,h,s,d]
__device__ float g_k[(size_t)BH_ * S_ * DH_];
__device__ float g_v[(size_t)BH_ * S_ * DH_];
__device__ float g_cos[NROT_ * DH_];
__device__ float g_sin[NROT_ * DH_];

// ---------------------------------------------------------------------------
// RoPE table: 2D rope, dim = Dh/2 = 32 per axis, 16 freqs each, repeat(2)
// ---------------------------------------------------------------------------
__global__ void rope_build_kernel() {
    int p = blockIdx.x;      // 0..575
    int d = threadIdx.x;     // 0..63
    int r = p / PT_, c = p % PT_;
    int tcoord = (d < 32) ? r : c;
    int dd = (d < 32) ? d : d - 32;
    int fi = dd >> 1;        // freq index 0..15
    float inv = powf(10000.0f, -(float)(2 * fi) / 32.0f);
    float ang = (float)tcoord * inv;
    g_cos[p * DH_ + d] = cosf(ang);
    g_sin[p * DH_ + d] = sinf(ang);
}

// ---------------------------------------------------------------------------
// Generic tiled fp32 GEMM with bias:  C[M,N] = A[M,K] @ B[K,N] + bias[N]
// 64x64 tile, BK=16, 256 threads, 4x4 per thread.
// ---------------------------------------------------------------------------
#define BM 64
#define BN 64
#define BK 16

__global__ void gemm_bias_kernel(const float* __restrict__ A,
                                 const float* __restrict__ Bm,
                                 const float* __restrict__ bias,
                                 float* __restrict__ C,
                                 int M, int N, int K) {
    __shared__ float As[BM][BK];
    __shared__ float Bs[BK][BN];
    int tid = threadIdx.x;
    int tx = tid & 15, ty = tid >> 4;
    int row0 = blockIdx.y * BM;
    int col0 = blockIdx.x * BN;

    float acc[4][4] = {};

    for (int k0 = 0; k0 < K; k0 += BK) {
        #pragma unroll
        for (int i = 0; i < 4; i++) {
            int idx = tid + i * 256;
            int r = idx >> 4, c = idx & 15;
            int gr = row0 + r;
            As[r][c] = (gr < M) ? A[(size_t)gr * K + k0 + c] : 0.0f;
        }
        #pragma unroll
        for (int i = 0; i < 4; i++) {
            int idx = tid + i * 256;
            int r = idx >> 6, c = idx & 63;
            Bs[r][c] = Bm[(size_t)(k0 + r) * N + col0 + c];
        }
        __syncthreads();
        #pragma unroll
        for (int kk = 0; kk < BK; kk++) {
            float a[4], b[4];
            #pragma unroll
            for (int i = 0; i < 4; i++) a[i] = As[ty * 4 + i][kk];
            #pragma unroll
            for (int j = 0; j < 4; j++) b[j] = Bs[kk][tx * 4 + j];
            #pragma unroll
            for (int i = 0; i < 4; i++)
                #pragma unroll
                for (int j = 0; j < 4; j++)
                    acc[i][j] += a[i] * b[j];
        }
        __syncthreads();
    }

    #pragma unroll
    for (int i = 0; i < 4; i++) {
        int gr = row0 + ty * 4 + i;
        if (gr >= M) continue;
        #pragma unroll
        for (int j = 0; j < 4; j++) {
            int gc = col0 + tx * 4 + j;
            C[(size_t)gr * N + gc] = acc[i][j] + bias[gc];
        }
    }
}

// ---------------------------------------------------------------------------
// Fused RoPE + transpose: g_qkv [b*s, 3*768] -> Q/K/V [b,h,s,64]
// grid = B*S, block = 768. thread t = h*64 + d.
// ---------------------------------------------------------------------------
__global__ void rope_transpose_kernel(const float* __restrict__ qkv,
                                      float* __restrict__ Q,
                                      float* __restrict__ K,
                                      float* __restrict__ V) {
    int bs = blockIdx.x;
    int b = bs / S_, s = bs % S_;
    int t = threadIdx.x;           // 0..767
    int h = t >> 6, d = t & 63;

    size_t base = (size_t)bs * QKV3_;
    float qv = qkv[base + t];
    float kv = qkv[base + E_ + t];
    float vv = qkv[base + 2 * E_ + t];

    if (s > 0) {
        int p = s - 1;
        float cs = g_cos[p * DH_ + d];
        float sn = g_sin[p * DH_ + d];
        int partner = t ^ 1;
        float qp = qkv[base + partner];
        float kp = qkv[base + E_ + partner];
        float sgn = (d & 1) ? 1.0f : -1.0f;
        qv = qv * cs + sgn * qp * sn;
        kv = kv * cs + sgn * kp * sn;
    }

    size_t o = ((size_t)(b * H_ + h) * S_ + s) * DH_ + d;
    Q[o] = qv;
    K[o] = kv;
    V[o] = vv;
}

// ---------------------------------------------------------------------------
// Flash attention: grid (n_qtiles, B*H), 256 threads.
// 64 q-rows x 64 k-cols tiles, online softmax, fp32.
// smem tiles padded (+1 float) for conflict-free column reads; smem stores
// are SCALAR (padded rows are not 16B-aligned for float4 stores).
// ---------------------------------------------------------------------------
#define FQ 64
#define FK 64
#define NTILES ((S_ + FK - 1) / FK)   // 10

__global__ __launch_bounds__(256, 2)
void flash_kernel(const float* __restrict__ Q,
                  const float* __restrict__ K,
                  const float* __restrict__ V,
                  const unsigned char* __restrict__ mask,
                  float* __restrict__ ctx) {
    int qb = blockIdx.x;              // q tile
    int bh = blockIdx.y;              // b*H + h
    int h = bh % H_, b = bh / H_;

    int tid = threadIdx.x;
    int tx = tid & 15, ty = tid >> 4; // 16x16 thread grid, 4x4 micro-tile

    __shared__ float Qs[FQ][DH_ + 1];
    __shared__ float Ks[FK][DH_ + 1];
    __shared__ float Vs[FK][DH_ + 1];
    __shared__ float Ps[FQ][FK + 1];
    __shared__ unsigned char ms[FK];

    const size_t bh_base = (size_t)bh * S_ * DH_;
    const int q0 = qb * FQ;

    // Load Q tile: float4 from global, scalar into padded smem
    #pragma unroll
    for (int i = 0; i < 4; i++) {
        int idx = tid + i * 256;
        int r = idx >> 4, c4 = idx & 15;
        float4 val = make_float4(0.f, 0.f, 0.f, 0.f);
        if (q0 + r < S_)
            val = *(const float4*)(Q + bh_base + (size_t)(q0 + r) * DH_ + c4 * 4);
        Qs[r][c4 * 4 + 0] = val.x;
        Qs[r][c4 * 4 + 1] = val.y;
        Qs[r][c4 * 4 + 2] = val.z;
        Qs[r][c4 * 4 + 3] = val.w;
    }
    __syncthreads();

    float m_st[4], l_st[4], O[4][4];
    #pragma unroll
    for (int i = 0; i < 4; i++) { m_st[i] = -1e30f; l_st[i] = 0.0f; }
    #pragma unroll
    for (int i = 0; i < 4; i++)
        #pragma unroll
        for (int j = 0; j < 4; j++) O[i][j] = 0.0f;

    for (int kt = 0; kt < NTILES; kt++) {
        int k0 = kt * FK;
        __syncthreads();   // previous PV gemm done before overwriting Ks/Vs

        // Load K and V tiles
        #pragma unroll
        for (int i = 0; i < 4; i++) {
            int idx = tid + i * 256;
            int r = idx >> 4, c4 = idx & 15;
            float4 kval = make_float4(0.f, 0.f, 0.f, 0.f);
            float4 vval = make_float4(0.f, 0.f, 0.f, 0.f);
            if (k0 + r < S_) {
                kval = *(const float4*)(K + bh_base + (size_t)(k0 + r) * DH_ + c4 * 4);
                vval = *(const float4*)(V + bh_base + (size_t)(k0 + r) * DH_ + c4 * 4);
            }
            Ks[r][c4 * 4 + 0] = kval.x;
            Ks[r][c4 * 4 + 1] = kval.y;
            Ks[r][c4 * 4 + 2] = kval.z;
            Ks[r][c4 * 4 + 3] = kval.w;
            Vs[r][c4 * 4 + 0] = vval.x;
            Vs[r][c4 * 4 + 1] = vval.y;
            Vs[r][c4 * 4 + 2] = vval.z;
            Vs[r][c4 * 4 + 3] = vval.w;
        }
        if (tid < FK)
            ms[tid] = (k0 + tid < S_) ? mask[b * S_ + k0 + tid] : (unsigned char)1;
        __syncthreads();

        // s = Q K^T * scale, with mask
        float s[4][4];
        #pragma unroll
        for (int i = 0; i < 4; i++)
            #pragma unroll
            for (int j = 0; j < 4; j++) s[i][j] = 0.0f;

        #pragma unroll 8
        for (int kk = 0; kk < DH_; kk++) {
            float a[4], bb[4];
            #pragma unroll
            for (int i = 0; i < 4; i++) a[i] = Qs[ty * 4 + i][kk];
            #pragma unroll
            for (int j = 0; j < 4; j++) bb[j] = Ks[tx * 4 + j][kk];
            #pragma unroll
            for (int i = 0; i < 4; i++)
                #pragma unroll
                for (int j = 0; j < 4; j++)
                    s[i][j] += a[i] * bb[j];
        }

        #pragma unroll
        for (int j = 0; j < 4; j++) {
            bool msk = ms[tx * 4 + j];
            #pragma unroll
            for (int i = 0; i < 4; i++)
                s[i][j] = msk ? -1e30f : s[i][j] * 0.125f;
        }

        // Online softmax: per-row reductions across the 16 tx threads
        #pragma unroll
        for (int i = 0; i < 4; i++) {
            float tm = fmaxf(fmaxf(s[i][0], s[i][1]), fmaxf(s[i][2], s[i][3]));
            #pragma unroll
            for (int o = 8; o > 0; o >>= 1)
                tm = fmaxf(tm, __shfl_xor_sync(0xffffffffu, tm, o, 16));
            float mnew = fmaxf(m_st[i], tm);
            float alpha = __expf(m_st[i] - mnew);
            float rs = 0.0f;
            #pragma unroll
            for (int j = 0; j < 4; j++) {
                float p = __expf(s[i][j] - mnew);
                s[i][j] = p;
                rs += p;
            }
            #pragma unroll
            for (int o = 8; o > 0; o >>= 1)
                rs += __shfl_xor_sync(0xffffffffu, rs, o, 16);
            l_st[i] = l_st[i] * alpha + rs;
            m_st[i] = mnew;
            #pragma unroll
            for (int j = 0; j < 4; j++) O[i][j] *= alpha;
        }

        // Store P tile
        #pragma unroll
        for (int i = 0; i < 4; i++)
            #pragma unroll
            for (int j = 0; j < 4; j++)
                Ps[ty * 4 + i][tx * 4 + j] = s[i][j];
        __syncthreads();

        // O += P @ V
        #pragma unroll 8
        for (int kk = 0; kk < FK; kk++) {
            float a[4], bb[4];
            #pragma unroll
            for (int i = 0; i < 4; i++) a[i] = Ps[ty * 4 + i][kk];
            #pragma unroll
            for (int j = 0; j < 4; j++) bb[j] = Vs[kk][tx * 4 + j];
            #pragma unroll
            for (int i = 0; i < 4; i++)
                #pragma unroll
                for (int j = 0; j < 4; j++)
                    O[i][j] += a[i] * bb[j];
        }
    }

    // Epilogue: normalize and write ctx [b*s, h*64+d] (float4, 16B aligned)
    #pragma unroll
    for (int i = 0; i < 4; i++) {
        int srow = q0 + ty * 4 + i;
        if (srow >= S_) continue;
        float inv = 1.0f / l_st[i];
        float4 o4 = make_float4(O[i][0] * inv, O[i][1] * inv,
                                O[i][2] * inv, O[i][3] * inv);
        *(float4*)(ctx + (size_t)(b * S_ + srow) * E_ + h * DH_ + tx * 4) = o4;
    }
}

// ---------------------------------------------------------------------------
// Launch
// ---------------------------------------------------------------------------
extern "C" void kernel_launch(void* const* d_in, const int* in_sizes, int n_in,
                              void* d_out, int out_size) {
    const float* x      = (const float*)d_in[0];
    const unsigned char* mask = (const unsigned char*)d_in[1];
    const float* W_qkv  = (const float*)d_in[2];
    const float* b_qkv  = (const float*)d_in[3];
    const float* W_proj = (const float*)d_in[4];
    const float* b_proj = (const float*)d_in[5];
    float* out = (float*)d_out;

    float* qkv; cudaGetSymbolAddress((void**)&qkv, g_qkv);
    float* ctx; cudaGetSymbolAddress((void**)&ctx, g_ctx);
    float* Qp;  cudaGetSymbolAddress((void**)&Qp, g_q);
    float* Kp;  cudaGetSymbolAddress((void**)&Kp, g_k);
    float* Vp;  cudaGetSymbolAddress((void**)&Vp, g_v);

    const int M = B_ * S_;   // 18464

    // 1) rope tables
    rope_build_kernel<<<NROT_, DH_>>>();

    // 2) qkv = x @ W_qkv + b_qkv   (M x 768 @ 768 x 2304)
    {
        dim3 grid(QKV3_ / BN, (M + BM - 1) / BM);
        gemm_bias_kernel<<<grid, 256>>>(x, W_qkv, b_qkv, qkv, M, QKV3_, E_);
    }

    // 3) rope + transpose to [b,h,s,d]
    rope_transpose_kernel<<<B_ * S_, E_>>>(qkv, Qp, Kp, Vp);

    // 4) flash attention
    {
        dim3 grid(NTILES, BH_);
        flash_kernel<<<grid, 256>>>(Qp, Kp, Vp, mask, ctx);
    }

    // 5) out = ctx @ W_proj + b_proj
    {
        dim3 grid(E_ / BN, (M + BM - 1) / BM);
        gemm_bias_kernel<<<grid, 256>>>(ctx, W_proj, b_proj, out, M, E_, E_);
    }
}

// round 4
// speedup vs baseline: 13.1777x; 1.6389x over previous
#include <cuda_runtime.h>
#include <cstdint>
#include <cstddef>

// Problem constants
#define B_    32
#define S_    577          // 24*24 + 1
#define E_    768
#define H_    12
#define DH_   64
#define PT_   24
#define QKV3_ 2304         // 3*E
#define NROT_ 576          // S-1 rope positions
#define BH_   (B_ * H_)    // 384

// Scratch (device globals; allocation-free per harness rules)
__device__ float g_qkv[(size_t)B_ * S_ * QKV3_];   // [b*s, (q|k|v) x h x d]
__device__ float g_ctx[(size_t)B_ * S_ * E_];      // [b*s, h*d]
__device__ float g_q[(size_t)BH_ * S_ * DH_];      // [b,h,s,d]
__device__ float g_k[(size_t)BH_ * S_ * DH_];
__device__ float g_v[(size_t)BH_ * S_ * DH_];
__device__ float g_cos[NROT_ * DH_];
__device__ float g_sin[NROT_ * DH_];

// ---------------------------------------------------------------------------
// RoPE table
// ---------------------------------------------------------------------------
__global__ void rope_build_kernel() {
    int p = blockIdx.x;      // 0..575
    int d = threadIdx.x;     // 0..63
    int r = p / PT_, c = p % PT_;
    int tcoord = (d < 32) ? r : c;
    int dd = (d < 32) ? d : d - 32;
    int fi = dd >> 1;        // freq index 0..15
    float inv = powf(10000.0f, -(float)(2 * fi) / 32.0f);
    float ang = (float)tcoord * inv;
    g_cos[p * DH_ + d] = cosf(ang);
    g_sin[p * DH_ + d] = sinf(ang);
}

// ---------------------------------------------------------------------------
// TF32 tensor-core GEMM with bias:  C[M,N] = A[M,K] @ B[K,N] + bias[N]
// 128x128 block tile, BK=16 double-buffered, 8 warps (2m x 4n),
// warp tile 64x32 via mma.sync.m16n8k8.tf32 (4 mtiles x 4 ntiles).
// ---------------------------------------------------------------------------
#define TBM 128
#define TBN 128
#define TBK 16

__device__ __forceinline__ uint32_t f2tf32(float x) {
    uint32_t r;
    asm("cvt.rna.tf32.f32 %0, %1;" : "=r"(r) : "f"(x));
    return r;
}

#define MMA_TF32(d, a, b)                                                  \
    asm volatile(                                                          \
        "mma.sync.aligned.m16n8k8.row.col.f32.tf32.tf32.f32 "              \
        "{%0,%1,%2,%3}, {%4,%5,%6,%7}, {%8,%9}, {%0,%1,%2,%3};"            \
        : "+f"(d[0]), "+f"(d[1]), "+f"(d[2]), "+f"(d[3])                   \
        : "r"(a[0]), "r"(a[1]), "r"(a[2]), "r"(a[3]), "r"(b[0]), "r"(b[1]))

__global__ __launch_bounds__(256, 2)
void gemm_tf32_kernel(const float* __restrict__ A,
                      const float* __restrict__ Bm,
                      const float* __restrict__ bias,
                      float* __restrict__ C,
                      int M, int N, int K) {
    // A stored transposed [k][m] for fragment loads; B as [k][n].
    __shared__ uint32_t As[2][TBK][TBM + 4];
    __shared__ uint32_t Bs[2][TBK][TBN + 4];

    const int tid  = threadIdx.x;
    const int lane = tid & 31;
    const int warp = tid >> 5;
    const int wm = (warp & 1) * 64;     // warp m offset in tile
    const int wn = (warp >> 1) * 32;    // warp n offset in tile
    const int g = lane >> 2;            // group id 0..7
    const int t = lane & 3;             // thread-in-group 0..3

    const int m0 = blockIdx.y * TBM;
    const int n0 = blockIdx.x * TBN;

    // Global load slots
    const int a_row0 = tid >> 2;            // 0..63
    const int a_c4   = tid & 3;             // k-quad 0..3
    const int a_row1 = a_row0 + 64;
    const int b_r0   = tid >> 5;            // 0..7
    const int b_c4   = tid & 31;            // n-quad 0..31
    const int b_r1   = b_r0 + 8;

    float4 ar[2], br[2];

    auto ldg = [&](int k0) {
        int gr0 = m0 + a_row0, gr1 = m0 + a_row1;
        ar[0] = (gr0 < M) ? *(const float4*)(A + (size_t)gr0 * K + k0 + a_c4 * 4)
                          : make_float4(0.f, 0.f, 0.f, 0.f);
        ar[1] = (gr1 < M) ? *(const float4*)(A + (size_t)gr1 * K + k0 + a_c4 * 4)
                          : make_float4(0.f, 0.f, 0.f, 0.f);
        br[0] = *(const float4*)(Bm + (size_t)(k0 + b_r0) * N + n0 + b_c4 * 4);
        br[1] = *(const float4*)(Bm + (size_t)(k0 + b_r1) * N + n0 + b_c4 * 4);
    };
    auto sts = [&](int buf) {
        // A: scalar stores, transposed
        As[buf][a_c4 * 4 + 0][a_row0] = f2tf32(ar[0].x);
        As[buf][a_c4 * 4 + 1][a_row0] = f2tf32(ar[0].y);
        As[buf][a_c4 * 4 + 2][a_row0] = f2tf32(ar[0].z);
        As[buf][a_c4 * 4 + 3][a_row0] = f2tf32(ar[0].w);
        As[buf][a_c4 * 4 + 0][a_row1] = f2tf32(ar[1].x);
        As[buf][a_c4 * 4 + 1][a_row1] = f2tf32(ar[1].y);
        As[buf][a_c4 * 4 + 2][a_row1] = f2tf32(ar[1].z);
        As[buf][a_c4 * 4 + 3][a_row1] = f2tf32(ar[1].w);
        // B: vector stores (row stride 132 floats = 528B, 16B multiple)
        uint4 u0 = make_uint4(f2tf32(br[0].x), f2tf32(br[0].y),
                              f2tf32(br[0].z), f2tf32(br[0].w));
        uint4 u1 = make_uint4(f2tf32(br[1].x), f2tf32(br[1].y),
                              f2tf32(br[1].z), f2tf32(br[1].w));
        *(uint4*)&Bs[buf][b_r0][b_c4 * 4] = u0;
        *(uint4*)&Bs[buf][b_r1][b_c4 * 4] = u1;
    };

    float acc[4][4][4];
    #pragma unroll
    for (int mt = 0; mt < 4; mt++)
        #pragma unroll
        for (int nt = 0; nt < 4; nt++)
            #pragma unroll
            for (int i = 0; i < 4; i++) acc[mt][nt][i] = 0.0f;

    const int NKT = K / TBK;   // 48 for K=768

    ldg(0);
    sts(0);
    __syncthreads();

    for (int kt = 0; kt < NKT; kt++) {
        int cur = kt & 1;
        if (kt + 1 < NKT) ldg((kt + 1) * TBK);

        #pragma unroll
        for (int ks = 0; ks < 2; ks++) {
            int k = ks * 8;
            uint32_t af[4][4], bf[4][2];
            #pragma unroll
            for (int mt = 0; mt < 4; mt++) {
                int rm = wm + mt * 16;
                af[mt][0] = As[cur][k + t][rm + g];
                af[mt][1] = As[cur][k + t][rm + g + 8];
                af[mt][2] = As[cur][k + t + 4][rm + g];
                af[mt][3] = As[cur][k + t + 4][rm + g + 8];
            }
            #pragma unroll
            for (int nt = 0; nt < 4; nt++) {
                int cn = wn + nt * 8;
                bf[nt][0] = Bs[cur][k + t][cn + g];
                bf[nt][1] = Bs[cur][k + t + 4][cn + g];
            }
            #pragma unroll
            for (int mt = 0; mt < 4; mt++)
                #pragma unroll
                for (int nt = 0; nt < 4; nt++)
                    MMA_TF32(acc[mt][nt], af[mt], bf[nt]);
        }

        if (kt + 1 < NKT) {
            sts(cur ^ 1);
            __syncthreads();
        }
    }

    // Epilogue: D layout c0,c1 -> (row g, cols 2t,2t+1); c2,c3 -> row g+8.
    #pragma unroll
    for (int nt = 0; nt < 4; nt++) {
        int gc = n0 + wn + nt * 8 + 2 * t;
        float bia0 = bias[gc], bia1 = bias[gc + 1];
        #pragma unroll
        for (int mt = 0; mt < 4; mt++) {
            int r0 = m0 + wm + mt * 16 + g;
            int r1 = r0 + 8;
            if (r0 < M) {
                float2 v = make_float2(acc[mt][nt][0] + bia0, acc[mt][nt][1] + bia1);
                *(float2*)(C + (size_t)r0 * N + gc) = v;
            }
            if (r1 < M) {
                float2 v = make_float2(acc[mt][nt][2] + bia0, acc[mt][nt][3] + bia1);
                *(float2*)(C + (size_t)r1 * N + gc) = v;
            }
        }
    }
}

// ---------------------------------------------------------------------------
// Fused RoPE + transpose: g_qkv [b*s, 3*768] -> Q/K/V [b,h,s,64]
// ---------------------------------------------------------------------------
__global__ void rope_transpose_kernel(const float* __restrict__ qkv,
                                      float* __restrict__ Q,
                                      float* __restrict__ K,
                                      float* __restrict__ V) {
    int bs = blockIdx.x;
    int b = bs / S_, s = bs % S_;
    int t = threadIdx.x;           // 0..767
    int h = t >> 6, d = t & 63;

    size_t base = (size_t)bs * QKV3_;
    float qv = qkv[base + t];
    float kv = qkv[base + E_ + t];
    float vv = qkv[base + 2 * E_ + t];

    if (s > 0) {
        int p = s - 1;
        float cs = g_cos[p * DH_ + d];
        float sn = g_sin[p * DH_ + d];
        int partner = t ^ 1;
        float qp = qkv[base + partner];
        float kp = qkv[base + E_ + partner];
        float sgn = (d & 1) ? 1.0f : -1.0f;
        qv = qv * cs + sgn * qp * sn;
        kv = kv * cs + sgn * kp * sn;
    }

    size_t o = ((size_t)(b * H_ + h) * S_ + s) * DH_ + d;
    Q[o] = qv;
    K[o] = kv;
    V[o] = vv;
}

// ---------------------------------------------------------------------------
// Flash attention: grid (n_qtiles, B*H), 256 threads. fp32.
// ---------------------------------------------------------------------------
#define FQ 64
#define FK 64
#define NTILES ((S_ + FK - 1) / FK)   // 10

__global__ __launch_bounds__(256, 2)
void flash_kernel(const float* __restrict__ Q,
                  const float* __restrict__ K,
                  const float* __restrict__ V,
                  const unsigned char* __restrict__ mask,
                  float* __restrict__ ctx) {
    int qb = blockIdx.x;
    int bh = blockIdx.y;
    int h = bh % H_, b = bh / H_;

    int tid = threadIdx.x;
    int tx = tid & 15, ty = tid >> 4;

    __shared__ float Qs[FQ][DH_ + 1];
    __shared__ float Ks[FK][DH_ + 1];
    __shared__ float Vs[FK][DH_ + 1];
    __shared__ float Ps[FQ][FK + 1];
    __shared__ unsigned char ms[FK];

    const size_t bh_base = (size_t)bh * S_ * DH_;
    const int q0 = qb * FQ;

    #pragma unroll
    for (int i = 0; i < 4; i++) {
        int idx = tid + i * 256;
        int r = idx >> 4, c4 = idx & 15;
        float4 val = make_float4(0.f, 0.f, 0.f, 0.f);
        if (q0 + r < S_)
            val = *(const float4*)(Q + bh_base + (size_t)(q0 + r) * DH_ + c4 * 4);
        Qs[r][c4 * 4 + 0] = val.x;
        Qs[r][c4 * 4 + 1] = val.y;
        Qs[r][c4 * 4 + 2] = val.z;
        Qs[r][c4 * 4 + 3] = val.w;
    }
    __syncthreads();

    float m_st[4], l_st[4], O[4][4];
    #pragma unroll
    for (int i = 0; i < 4; i++) { m_st[i] = -1e30f; l_st[i] = 0.0f; }
    #pragma unroll
    for (int i = 0; i < 4; i++)
        #pragma unroll
        for (int j = 0; j < 4; j++) O[i][j] = 0.0f;

    for (int kt = 0; kt < NTILES; kt++) {
        int k0 = kt * FK;
        __syncthreads();

        #pragma unroll
        for (int i = 0; i < 4; i++) {
            int idx = tid + i * 256;
            int r = idx >> 4, c4 = idx & 15;
            float4 kval = make_float4(0.f, 0.f, 0.f, 0.f);
            float4 vval = make_float4(0.f, 0.f, 0.f, 0.f);
            if (k0 + r < S_) {
                kval = *(const float4*)(K + bh_base + (size_t)(k0 + r) * DH_ + c4 * 4);
                vval = *(const float4*)(V + bh_base + (size_t)(k0 + r) * DH_ + c4 * 4);
            }
            Ks[r][c4 * 4 + 0] = kval.x;
            Ks[r][c4 * 4 + 1] = kval.y;
            Ks[r][c4 * 4 + 2] = kval.z;
            Ks[r][c4 * 4 + 3] = kval.w;
            Vs[r][c4 * 4 + 0] = vval.x;
            Vs[r][c4 * 4 + 1] = vval.y;
            Vs[r][c4 * 4 + 2] = vval.z;
            Vs[r][c4 * 4 + 3] = vval.w;
        }
        if (tid < FK)
            ms[tid] = (k0 + tid < S_) ? mask[b * S_ + k0 + tid] : (unsigned char)1;
        __syncthreads();

        float s[4][4];
        #pragma unroll
        for (int i = 0; i < 4; i++)
            #pragma unroll
            for (int j = 0; j < 4; j++) s[i][j] = 0.0f;

        #pragma unroll 8
        for (int kk = 0; kk < DH_; kk++) {
            float a[4], bb[4];
            #pragma unroll
            for (int i = 0; i < 4; i++) a[i] = Qs[ty * 4 + i][kk];
            #pragma unroll
            for (int j = 0; j < 4; j++) bb[j] = Ks[tx * 4 + j][kk];
            #pragma unroll
            for (int i = 0; i < 4; i++)
                #pragma unroll
                for (int j = 0; j < 4; j++)
                    s[i][j] += a[i] * bb[j];
        }

        #pragma unroll
        for (int j = 0; j < 4; j++) {
            bool msk = ms[tx * 4 + j];
            #pragma unroll
            for (int i = 0; i < 4; i++)
                s[i][j] = msk ? -1e30f : s[i][j] * 0.125f;
        }

        #pragma unroll
        for (int i = 0; i < 4; i++) {
            float tm = fmaxf(fmaxf(s[i][0], s[i][1]), fmaxf(s[i][2], s[i][3]));
            #pragma unroll
            for (int o = 8; o > 0; o >>= 1)
                tm = fmaxf(tm, __shfl_xor_sync(0xffffffffu, tm, o, 16));
            float mnew = fmaxf(m_st[i], tm);
            float alpha = __expf(m_st[i] - mnew);
            float rs = 0.0f;
            #pragma unroll
            for (int j = 0; j < 4; j++) {
                float p = __expf(s[i][j] - mnew);
                s[i][j] = p;
                rs += p;
            }
            #pragma unroll
            for (int o = 8; o > 0; o >>= 1)
                rs += __shfl_xor_sync(0xffffffffu, rs, o, 16);
            l_st[i] = l_st[i] * alpha + rs;
            m_st[i] = mnew;
            #pragma unroll
            for (int j = 0; j < 4; j++) O[i][j] *= alpha;
        }

        #pragma unroll
        for (int i = 0; i < 4; i++)
            #pragma unroll
            for (int j = 0; j < 4; j++)
                Ps[ty * 4 + i][tx * 4 + j] = s[i][j];
        __syncthreads();

        #pragma unroll 8
        for (int kk = 0; kk < FK; kk++) {
            float a[4], bb[4];
            #pragma unroll
            for (int i = 0; i < 4; i++) a[i] = Ps[ty * 4 + i][kk];
            #pragma unroll
            for (int j = 0; j < 4; j++) bb[j] = Vs[kk][tx * 4 + j];
            #pragma unroll
            for (int i = 0; i < 4; i++)
                #pragma unroll
                for (int j = 0; j < 4; j++)
                    O[i][j] += a[i] * bb[j];
        }
    }

    #pragma unroll
    for (int i = 0; i < 4; i++) {
        int srow = q0 + ty * 4 + i;
        if (srow >= S_) continue;
        float inv = 1.0f / l_st[i];
        float4 o4 = make_float4(O[i][0] * inv, O[i][1] * inv,
                                O[i][2] * inv, O[i][3] * inv);
        *(float4*)(ctx + (size_t)(b * S_ + srow) * E_ + h * DH_ + tx * 4) = o4;
    }
}

// ---------------------------------------------------------------------------
// Launch
// ---------------------------------------------------------------------------
extern "C" void kernel_launch(void* const* d_in, const int* in_sizes, int n_in,
                              void* d_out, int out_size) {
    const float* x      = (const float*)d_in[0];
    const unsigned char* mask = (const unsigned char*)d_in[1];
    const float* W_qkv  = (const float*)d_in[2];
    const float* b_qkv  = (const float*)d_in[3];
    const float* W_proj = (const float*)d_in[4];
    const float* b_proj = (const float*)d_in[5];
    float* out = (float*)d_out;

    float* qkv; cudaGetSymbolAddress((void**)&qkv, g_qkv);
    float* ctx; cudaGetSymbolAddress((void**)&ctx, g_ctx);
    float* Qp;  cudaGetSymbolAddress((void**)&Qp, g_q);
    float* Kp;  cudaGetSymbolAddress((void**)&Kp, g_k);
    float* Vp;  cudaGetSymbolAddress((void**)&Vp, g_v);

    const int M = B_ * S_;   // 18464

    // 1) rope tables
    rope_build_kernel<<<NROT_, DH_>>>();

    // 2) qkv = x @ W_qkv + b_qkv  (tf32 tensor cores)
    {
        dim3 grid(QKV3_ / TBN, (M + TBM - 1) / TBM);
        gemm_tf32_kernel<<<grid, 256>>>(x, W_qkv, b_qkv, qkv, M, QKV3_, E_);
    }

    // 3) rope + transpose to [b,h,s,d]
    rope_transpose_kernel<<<B_ * S_, E_>>>(qkv, Qp, Kp, Vp);

    // 4) flash attention
    {
        dim3 grid(NTILES, BH_);
        flash_kernel<<<grid, 256>>>(Qp, Kp, Vp, mask, ctx);
    }

    // 5) out = ctx @ W_proj + b_proj  (tf32 tensor cores)
    {
        dim3 grid(E_ / TBN, (M + TBM - 1) / TBM);
        gemm_tf32_kernel<<<grid, 256>>>(ctx, W_proj, b_proj, out, M, E_, E_);
    }
}

// round 5
// speedup vs baseline: 23.2708x; 1.7659x over previous
#include <cuda_runtime.h>
#include <cstdint>
#include <cstddef>

// Problem constants
#define B_    32
#define S_    577          // 24*24 + 1
#define E_    768
#define H_    12
#define DH_   64
#define PT_   24
#define QKV3_ 2304         // 3*E
#define NROT_ 576          // S-1 rope positions
#define BH_   (B_ * H_)    // 384

// Scratch (device globals; allocation-free per harness rules)
__device__ float g_qkv[(size_t)B_ * S_ * QKV3_];   // [b*s, (q|k|v) x h x d]
__device__ float g_ctx[(size_t)B_ * S_ * E_];      // [b*s, h*d]
__device__ float g_q[(size_t)BH_ * S_ * DH_];      // [b,h,s,d]
__device__ float g_k[(size_t)BH_ * S_ * DH_];
__device__ float g_v[(size_t)BH_ * S_ * DH_];
__device__ float g_cos[NROT_ * DH_];
__device__ float g_sin[NROT_ * DH_];

// ---------------------------------------------------------------------------
// RoPE table
// ---------------------------------------------------------------------------
__global__ void rope_build_kernel() {
    int p = blockIdx.x;      // 0..575
    int d = threadIdx.x;     // 0..63
    int r = p / PT_, c = p % PT_;
    int tcoord = (d < 32) ? r : c;
    int dd = (d < 32) ? d : d - 32;
    int fi = dd >> 1;        // freq index 0..15
    float inv = powf(10000.0f, -(float)(2 * fi) / 32.0f);
    float ang = (float)tcoord * inv;
    g_cos[p * DH_ + d] = cosf(ang);
    g_sin[p * DH_ + d] = sinf(ang);
}

// ---------------------------------------------------------------------------
// Shared tf32 helpers
// ---------------------------------------------------------------------------
__device__ __forceinline__ uint32_t f2tf32(float x) {
    uint32_t r;
    asm("cvt.rna.tf32.f32 %0, %1;" : "=r"(r) : "f"(x));
    return r;
}

#define MMA_TF32(d, a, b)                                                  \
    asm volatile(                                                          \
        "mma.sync.aligned.m16n8k8.row.col.f32.tf32.tf32.f32 "              \
        "{%0,%1,%2,%3}, {%4,%5,%6,%7}, {%8,%9}, {%0,%1,%2,%3};"            \
        : "+f"(d[0]), "+f"(d[1]), "+f"(d[2]), "+f"(d[3])                   \
        : "r"(a[0]), "r"(a[1]), "r"(a[2]), "r"(a[3]), "r"(b[0]), "r"(b[1]))

// ---------------------------------------------------------------------------
// TF32 tensor-core GEMM with bias:  C[M,N] = A[M,K] @ B[K,N] + bias[N]
// ---------------------------------------------------------------------------
#define TBM 128
#define TBN 128
#define TBK 16

__global__ __launch_bounds__(256, 2)
void gemm_tf32_kernel(const float* __restrict__ A,
                      const float* __restrict__ Bm,
                      const float* __restrict__ bias,
                      float* __restrict__ C,
                      int M, int N, int K) {
    __shared__ uint32_t As[2][TBK][TBM + 4];
    __shared__ uint32_t Bs[2][TBK][TBN + 4];

    const int tid  = threadIdx.x;
    const int lane = tid & 31;
    const int warp = tid >> 5;
    const int wm = (warp & 1) * 64;
    const int wn = (warp >> 1) * 32;
    const int g = lane >> 2;
    const int t = lane & 3;

    const int m0 = blockIdx.y * TBM;
    const int n0 = blockIdx.x * TBN;

    const int a_row0 = tid >> 2;
    const int a_c4   = tid & 3;
    const int a_row1 = a_row0 + 64;
    const int b_r0   = tid >> 5;
    const int b_c4   = tid & 31;
    const int b_r1   = b_r0 + 8;

    float4 ar[2], br[2];

    auto ldg = [&](int k0) {
        int gr0 = m0 + a_row0, gr1 = m0 + a_row1;
        ar[0] = (gr0 < M) ? *(const float4*)(A + (size_t)gr0 * K + k0 + a_c4 * 4)
                          : make_float4(0.f, 0.f, 0.f, 0.f);
        ar[1] = (gr1 < M) ? *(const float4*)(A + (size_t)gr1 * K + k0 + a_c4 * 4)
                          : make_float4(0.f, 0.f, 0.f, 0.f);
        br[0] = *(const float4*)(Bm + (size_t)(k0 + b_r0) * N + n0 + b_c4 * 4);
        br[1] = *(const float4*)(Bm + (size_t)(k0 + b_r1) * N + n0 + b_c4 * 4);
    };
    auto sts = [&](int buf) {
        As[buf][a_c4 * 4 + 0][a_row0] = f2tf32(ar[0].x);
        As[buf][a_c4 * 4 + 1][a_row0] = f2tf32(ar[0].y);
        As[buf][a_c4 * 4 + 2][a_row0] = f2tf32(ar[0].z);
        As[buf][a_c4 * 4 + 3][a_row0] = f2tf32(ar[0].w);
        As[buf][a_c4 * 4 + 0][a_row1] = f2tf32(ar[1].x);
        As[buf][a_c4 * 4 + 1][a_row1] = f2tf32(ar[1].y);
        As[buf][a_c4 * 4 + 2][a_row1] = f2tf32(ar[1].z);
        As[buf][a_c4 * 4 + 3][a_row1] = f2tf32(ar[1].w);
        uint4 u0 = make_uint4(f2tf32(br[0].x), f2tf32(br[0].y),
                              f2tf32(br[0].z), f2tf32(br[0].w));
        uint4 u1 = make_uint4(f2tf32(br[1].x), f2tf32(br[1].y),
                              f2tf32(br[1].z), f2tf32(br[1].w));
        *(uint4*)&Bs[buf][b_r0][b_c4 * 4] = u0;
        *(uint4*)&Bs[buf][b_r1][b_c4 * 4] = u1;
    };

    float acc[4][4][4];
    #pragma unroll
    for (int mt = 0; mt < 4; mt++)
        #pragma unroll
        for (int nt = 0; nt < 4; nt++)
            #pragma unroll
            for (int i = 0; i < 4; i++) acc[mt][nt][i] = 0.0f;

    const int NKT = K / TBK;

    ldg(0);
    sts(0);
    __syncthreads();

    for (int kt = 0; kt < NKT; kt++) {
        int cur = kt & 1;
        if (kt + 1 < NKT) ldg((kt + 1) * TBK);

        #pragma unroll
        for (int ks = 0; ks < 2; ks++) {
            int k = ks * 8;
            uint32_t af[4][4], bf[4][2];
            #pragma unroll
            for (int mt = 0; mt < 4; mt++) {
                int rm = wm + mt * 16;
                af[mt][0] = As[cur][k + t][rm + g];
                af[mt][1] = As[cur][k + t][rm + g + 8];
                af[mt][2] = As[cur][k + t + 4][rm + g];
                af[mt][3] = As[cur][k + t + 4][rm + g + 8];
            }
            #pragma unroll
            for (int nt = 0; nt < 4; nt++) {
                int cn = wn + nt * 8;
                bf[nt][0] = Bs[cur][k + t][cn + g];
                bf[nt][1] = Bs[cur][k + t + 4][cn + g];
            }
            #pragma unroll
            for (int mt = 0; mt < 4; mt++)
                #pragma unroll
                for (int nt = 0; nt < 4; nt++)
                    MMA_TF32(acc[mt][nt], af[mt], bf[nt]);
        }

        if (kt + 1 < NKT) {
            sts(cur ^ 1);
            __syncthreads();
        }
    }

    #pragma unroll
    for (int nt = 0; nt < 4; nt++) {
        int gc = n0 + wn + nt * 8 + 2 * t;
        float bia0 = bias[gc], bia1 = bias[gc + 1];
        #pragma unroll
        for (int mt = 0; mt < 4; mt++) {
            int r0 = m0 + wm + mt * 16 + g;
            int r1 = r0 + 8;
            if (r0 < M) {
                float2 v = make_float2(acc[mt][nt][0] + bia0, acc[mt][nt][1] + bia1);
                *(float2*)(C + (size_t)r0 * N + gc) = v;
            }
            if (r1 < M) {
                float2 v = make_float2(acc[mt][nt][2] + bia0, acc[mt][nt][3] + bia1);
                *(float2*)(C + (size_t)r1 * N + gc) = v;
            }
        }
    }
}

// ---------------------------------------------------------------------------
// Fused RoPE + transpose: g_qkv [b*s, 3*768] -> Q/K/V [b,h,s,64]
// ---------------------------------------------------------------------------
__global__ void rope_transpose_kernel(const float* __restrict__ qkv,
                                      float* __restrict__ Q,
                                      float* __restrict__ K,
                                      float* __restrict__ V) {
    int bs = blockIdx.x;
    int b = bs / S_, s = bs % S_;
    int t = threadIdx.x;           // 0..767
    int h = t >> 6, d = t & 63;

    size_t base = (size_t)bs * QKV3_;
    float qv = qkv[base + t];
    float kv = qkv[base + E_ + t];
    float vv = qkv[base + 2 * E_ + t];

    if (s > 0) {
        int p = s - 1;
        float cs = g_cos[p * DH_ + d];
        float sn = g_sin[p * DH_ + d];
        int partner = t ^ 1;
        float qp = qkv[base + partner];
        float kp = qkv[base + E_ + partner];
        float sgn = (d & 1) ? 1.0f : -1.0f;
        qv = qv * cs + sgn * qp * sn;
        kv = kv * cs + sgn * kp * sn;
    }

    size_t o = ((size_t)(b * H_ + h) * S_ + s) * DH_ + d;
    Q[o] = qv;
    K[o] = kv;
    V[o] = vv;
}

// ---------------------------------------------------------------------------
// TF32 tensor-core flash attention.
// 128 threads = 4 warps; warp w owns q-rows [w*16, w*16+16).
// FQ=64 q rows per block, FK=64 keys per tile, 10 tiles.
// Pads: 68 (stride%32==4 -> bank 4g+t) for Q/K/P; 72 (stride%32==8 ->
// bank 8t+g) for V whose fragment access is [k][n].
// ---------------------------------------------------------------------------
#define FQ 64
#define FK 64
#define NTILES ((S_ + FK - 1) / FK)   // 10
#define PADA 68
#define PADV 72

__global__ __launch_bounds__(128, 1)
void flash_tf32_kernel(const float* __restrict__ Q,
                       const float* __restrict__ K,
                       const float* __restrict__ V,
                       const unsigned char* __restrict__ mask,
                       float* __restrict__ ctx) {
    int qb = blockIdx.x;
    int bh = blockIdx.y;
    int h = bh % H_, b = bh / H_;

    int tid  = threadIdx.x;
    int lane = tid & 31;
    int warp = tid >> 5;
    int g = lane >> 2;      // 0..7
    int t = lane & 3;       // 0..3
    int rm = warp * 16;     // warp's q-row base within tile

    __shared__ uint32_t Qs[FQ][PADA];
    __shared__ uint32_t Ks[FK][PADA];
    __shared__ uint32_t Vs[FK][PADV];
    __shared__ uint32_t Ps[FQ][PADA];
    __shared__ unsigned char ms[FK];

    const size_t bh_base = (size_t)bh * S_ * DH_;
    const int q0 = qb * FQ;

    // Load + convert Q tile: 64 rows x 16 float4 = 1024 slots, 8 per thread
    #pragma unroll
    for (int i = 0; i < 8; i++) {
        int idx = tid + i * 128;
        int r = idx >> 4, c4 = idx & 15;
        float4 v = make_float4(0.f, 0.f, 0.f, 0.f);
        if (q0 + r < S_)
            v = *(const float4*)(Q + bh_base + (size_t)(q0 + r) * DH_ + c4 * 4);
        uint4 u = make_uint4(f2tf32(v.x), f2tf32(v.y), f2tf32(v.z), f2tf32(v.w));
        *(uint4*)&Qs[r][c4 * 4] = u;
    }

    float m_st[2] = {-1e30f, -1e30f};
    float l_st[2] = {0.0f, 0.0f};
    float O[8][4];
    #pragma unroll
    for (int nt = 0; nt < 8; nt++)
        #pragma unroll
        for (int i = 0; i < 4; i++) O[nt][i] = 0.0f;

    for (int kt = 0; kt < NTILES; kt++) {
        int k0 = kt * FK;
        __syncthreads();   // prev PV done (and Q ready on first iter)

        // Load + convert K, V tiles
        #pragma unroll
        for (int i = 0; i < 8; i++) {
            int idx = tid + i * 128;
            int r = idx >> 4, c4 = idx & 15;
            float4 kv = make_float4(0.f, 0.f, 0.f, 0.f);
            float4 vv = make_float4(0.f, 0.f, 0.f, 0.f);
            if (k0 + r < S_) {
                kv = *(const float4*)(K + bh_base + (size_t)(k0 + r) * DH_ + c4 * 4);
                vv = *(const float4*)(V + bh_base + (size_t)(k0 + r) * DH_ + c4 * 4);
            }
            uint4 ku = make_uint4(f2tf32(kv.x), f2tf32(kv.y), f2tf32(kv.z), f2tf32(kv.w));
            uint4 vu = make_uint4(f2tf32(vv.x), f2tf32(vv.y), f2tf32(vv.z), f2tf32(vv.w));
            *(uint4*)&Ks[r][c4 * 4] = ku;
            *(uint4*)&Vs[r][c4 * 4] = vu;
        }
        if (tid < FK)
            ms[tid] = (k0 + tid < S_) ? mask[b * S_ + k0 + tid] : (unsigned char)1;
        __syncthreads();

        // ---- S = Q K^T (16 x 64 per warp) ----
        float s[8][4];
        #pragma unroll
        for (int nt = 0; nt < 8; nt++)
            #pragma unroll
            for (int i = 0; i < 4; i++) s[nt][i] = 0.0f;

        #pragma unroll
        for (int ks = 0; ks < 8; ks++) {
            int kk = ks * 8;
            uint32_t af[4];
            af[0] = Qs[rm + g][kk + t];
            af[1] = Qs[rm + g + 8][kk + t];
            af[2] = Qs[rm + g][kk + t + 4];
            af[3] = Qs[rm + g + 8][kk + t + 4];
            #pragma unroll
            for (int nt = 0; nt < 8; nt++) {
                uint32_t bf[2];
                bf[0] = Ks[nt * 8 + g][kk + t];
                bf[1] = Ks[nt * 8 + g][kk + t + 4];
                MMA_TF32(s[nt], af, bf);
            }
        }

        // ---- scale + mask ----
        #pragma unroll
        for (int nt = 0; nt < 8; nt++) {
            int c = nt * 8 + 2 * t;
            bool mk0 = ms[c], mk1 = ms[c + 1];
            s[nt][0] = mk0 ? -1e30f : s[nt][0] * 0.125f;
            s[nt][1] = mk1 ? -1e30f : s[nt][1] * 0.125f;
            s[nt][2] = mk0 ? -1e30f : s[nt][2] * 0.125f;
            s[nt][3] = mk1 ? -1e30f : s[nt][3] * 0.125f;
        }

        // ---- online softmax: rows g (c0,c1) and g+8 (c2,c3) ----
        float tm0 = -1e30f, tm1 = -1e30f;
        #pragma unroll
        for (int nt = 0; nt < 8; nt++) {
            tm0 = fmaxf(tm0, fmaxf(s[nt][0], s[nt][1]));
            tm1 = fmaxf(tm1, fmaxf(s[nt][2], s[nt][3]));
        }
        tm0 = fmaxf(tm0, __shfl_xor_sync(0xffffffffu, tm0, 1));
        tm0 = fmaxf(tm0, __shfl_xor_sync(0xffffffffu, tm0, 2));
        tm1 = fmaxf(tm1, __shfl_xor_sync(0xffffffffu, tm1, 1));
        tm1 = fmaxf(tm1, __shfl_xor_sync(0xffffffffu, tm1, 2));

        float mn0 = fmaxf(m_st[0], tm0);
        float mn1 = fmaxf(m_st[1], tm1);
        float al0 = __expf(m_st[0] - mn0);
        float al1 = __expf(m_st[1] - mn1);

        float rs0 = 0.0f, rs1 = 0.0f;
        #pragma unroll
        for (int nt = 0; nt < 8; nt++) {
            float p0 = __expf(s[nt][0] - mn0);
            float p1 = __expf(s[nt][1] - mn0);
            float p2 = __expf(s[nt][2] - mn1);
            float p3 = __expf(s[nt][3] - mn1);
            s[nt][0] = p0; s[nt][1] = p1; s[nt][2] = p2; s[nt][3] = p3;
            rs0 += p0 + p1;
            rs1 += p2 + p3;
        }
        rs0 += __shfl_xor_sync(0xffffffffu, rs0, 1);
        rs0 += __shfl_xor_sync(0xffffffffu, rs0, 2);
        rs1 += __shfl_xor_sync(0xffffffffu, rs1, 1);
        rs1 += __shfl_xor_sync(0xffffffffu, rs1, 2);

        l_st[0] = l_st[0] * al0 + rs0;
        l_st[1] = l_st[1] * al1 + rs1;
        m_st[0] = mn0;
        m_st[1] = mn1;

        #pragma unroll
        for (int nt = 0; nt < 8; nt++) {
            O[nt][0] *= al0;
            O[nt][1] *= al0;
            O[nt][2] *= al1;
            O[nt][3] *= al1;
        }

        // ---- store P (tf32) to warp-private smem rows ----
        #pragma unroll
        for (int nt = 0; nt < 8; nt++) {
            int c = nt * 8 + 2 * t;
            *(uint2*)&Ps[rm + g][c]     = make_uint2(f2tf32(s[nt][0]), f2tf32(s[nt][1]));
            *(uint2*)&Ps[rm + g + 8][c] = make_uint2(f2tf32(s[nt][2]), f2tf32(s[nt][3]));
        }
        __syncwarp();

        // ---- O += P @ V ----
        #pragma unroll
        for (int ks = 0; ks < 8; ks++) {
            int kk = ks * 8;
            uint32_t af[4];
            af[0] = Ps[rm + g][kk + t];
            af[1] = Ps[rm + g + 8][kk + t];
            af[2] = Ps[rm + g][kk + t + 4];
            af[3] = Ps[rm + g + 8][kk + t + 4];
            #pragma unroll
            for (int nt = 0; nt < 8; nt++) {
                uint32_t bf[2];
                bf[0] = Vs[kk + t][nt * 8 + g];
                bf[1] = Vs[kk + t + 4][nt * 8 + g];
                MMA_TF32(O[nt], af, bf);
            }
        }
    }

    // ---- epilogue ----
    float inv0 = 1.0f / l_st[0];
    float inv1 = 1.0f / l_st[1];
    int r0 = q0 + rm + g;
    int r1 = r0 + 8;
    #pragma unroll
    for (int nt = 0; nt < 8; nt++) {
        int col = h * DH_ + nt * 8 + 2 * t;
        if (r0 < S_) {
            float2 v = make_float2(O[nt][0] * inv0, O[nt][1] * inv0);
            *(float2*)(ctx + (size_t)(b * S_ + r0) * E_ + col) = v;
        }
        if (r1 < S_) {
            float2 v = make_float2(O[nt][2] * inv1, O[nt][3] * inv1);
            *(float2*)(ctx + (size_t)(b * S_ + r1) * E_ + col) = v;
        }
    }
}

// ---------------------------------------------------------------------------
// Launch
// ---------------------------------------------------------------------------
extern "C" void kernel_launch(void* const* d_in, const int* in_sizes, int n_in,
                              void* d_out, int out_size) {
    const float* x      = (const float*)d_in[0];
    const unsigned char* mask = (const unsigned char*)d_in[1];
    const float* W_qkv  = (const float*)d_in[2];
    const float* b_qkv  = (const float*)d_in[3];
    const float* W_proj = (const float*)d_in[4];
    const float* b_proj = (const float*)d_in[5];
    float* out = (float*)d_out;

    float* qkv; cudaGetSymbolAddress((void**)&qkv, g_qkv);
    float* ctx; cudaGetSymbolAddress((void**)&ctx, g_ctx);
    float* Qp;  cudaGetSymbolAddress((void**)&Qp, g_q);
    float* Kp;  cudaGetSymbolAddress((void**)&Kp, g_k);
    float* Vp;  cudaGetSymbolAddress((void**)&Vp, g_v);

    const int M = B_ * S_;   // 18464

    // 1) rope tables
    rope_build_kernel<<<NROT_, DH_>>>();

    // 2) qkv = x @ W_qkv + b_qkv  (tf32 tensor cores)
    {
        dim3 grid(QKV3_ / TBN, (M + TBM - 1) / TBM);
        gemm_tf32_kernel<<<grid, 256>>>(x, W_qkv, b_qkv, qkv, M, QKV3_, E_);
    }

    // 3) rope + transpose to [b,h,s,d]
    rope_transpose_kernel<<<B_ * S_, E_>>>(qkv, Qp, Kp, Vp);

    // 4) flash attention (tf32 tensor cores)
    {
        dim3 grid(NTILES, BH_);
        flash_tf32_kernel<<<grid, 128>>>(Qp, Kp, Vp, mask, ctx);
    }

    // 5) out = ctx @ W_proj + b_proj  (tf32 tensor cores)
    {
        dim3 grid(E_ / TBN, (M + TBM - 1) / TBM);
        gemm_tf32_kernel<<<grid, 256>>>(ctx, W_proj, b_proj, out, M, E_, E_);
    }
}

// round 6
// speedup vs baseline: 27.5832x; 1.1853x over previous
#include <cuda_runtime.h>
#include <cstdint>
#include <cstddef>

// Problem constants
#define B_    32
#define S_    577          // 24*24 + 1
#define E_    768
#define H_    12
#define DH_   64
#define PT_   24
#define QKV3_ 2304         // 3*E
#define NROT_ 576          // S-1 rope positions
#define BH_   (B_ * H_)    // 384

// Scratch (device globals; allocation-free per harness rules)
__device__ float g_ctx[(size_t)B_ * S_ * E_];      // [b*s, h*d]
__device__ float g_q[(size_t)BH_ * S_ * DH_];      // [b,h,s,d]
__device__ float g_k[(size_t)BH_ * S_ * DH_];
__device__ float g_v[(size_t)BH_ * S_ * DH_];
__device__ float g_cos[NROT_ * DH_];
__device__ float g_sin[NROT_ * DH_];

// ---------------------------------------------------------------------------
// RoPE table
// ---------------------------------------------------------------------------
__global__ void rope_build_kernel() {
    int p = blockIdx.x;      // 0..575
    int d = threadIdx.x;     // 0..63
    int r = p / PT_, c = p % PT_;
    int tcoord = (d < 32) ? r : c;
    int dd = (d < 32) ? d : d - 32;
    int fi = dd >> 1;        // freq index 0..15
    float inv = powf(10000.0f, -(float)(2 * fi) / 32.0f);
    float ang = (float)tcoord * inv;
    g_cos[p * DH_ + d] = cosf(ang);
    g_sin[p * DH_ + d] = sinf(ang);
}

// ---------------------------------------------------------------------------
// Shared tf32 helpers
// ---------------------------------------------------------------------------
__device__ __forceinline__ uint32_t f2tf32(float x) {
    uint32_t r;
    asm("cvt.rna.tf32.f32 %0, %1;" : "=r"(r) : "f"(x));
    return r;
}

#define MMA_TF32(d, a, b)                                                  \
    asm volatile(                                                          \
        "mma.sync.aligned.m16n8k8.row.col.f32.tf32.tf32.f32 "              \
        "{%0,%1,%2,%3}, {%4,%5,%6,%7}, {%8,%9}, {%0,%1,%2,%3};"            \
        : "+f"(d[0]), "+f"(d[1]), "+f"(d[2]), "+f"(d[3])                   \
        : "r"(a[0]), "r"(a[1]), "r"(a[2]), "r"(a[3]), "r"(b[0]), "r"(b[1]))

// ---------------------------------------------------------------------------
// TF32 GEMM mainloop shared by both GEMM kernels.
// 128x128 tile, BK=16 double-buffered, 8 warps (2m x 4n), warp 64x32.
// Pad +8: fragment-load bank = 8t+g (bijective) -> conflict-free.
// ---------------------------------------------------------------------------
#define TBM 128
#define TBN 128
#define TBK 16
#define TPAD 8

struct GemmCtx {
    int wm, wn, g, t, m0, n0;
};

// Computes acc for tile (m0,n0). As/Bs provided by caller's smem.
__device__ __forceinline__ void gemm_mainloop(
    const float* __restrict__ A, const float* __restrict__ Bm,
    int M, int N, int K, const GemmCtx& cx,
    uint32_t (*As)[TBK][TBM + TPAD], uint32_t (*Bs)[TBK][TBN + TPAD],
    float acc[4][4][4])
{
    const int tid = threadIdx.x;
    const int a_row0 = tid >> 2;
    const int a_c4   = tid & 3;
    const int a_row1 = a_row0 + 64;
    const int b_r0   = tid >> 5;
    const int b_c4   = tid & 31;
    const int b_r1   = b_r0 + 8;

    float4 ar[2], br[2];

    auto ldg = [&](int k0) {
        int gr0 = cx.m0 + a_row0, gr1 = cx.m0 + a_row1;
        ar[0] = (gr0 < M) ? *(const float4*)(A + (size_t)gr0 * K + k0 + a_c4 * 4)
                          : make_float4(0.f, 0.f, 0.f, 0.f);
        ar[1] = (gr1 < M) ? *(const float4*)(A + (size_t)gr1 * K + k0 + a_c4 * 4)
                          : make_float4(0.f, 0.f, 0.f, 0.f);
        br[0] = *(const float4*)(Bm + (size_t)(k0 + b_r0) * N + cx.n0 + b_c4 * 4);
        br[1] = *(const float4*)(Bm + (size_t)(k0 + b_r1) * N + cx.n0 + b_c4 * 4);
    };
    auto sts = [&](int buf) {
        As[buf][a_c4 * 4 + 0][a_row0] = f2tf32(ar[0].x);
        As[buf][a_c4 * 4 + 1][a_row0] = f2tf32(ar[0].y);
        As[buf][a_c4 * 4 + 2][a_row0] = f2tf32(ar[0].z);
        As[buf][a_c4 * 4 + 3][a_row0] = f2tf32(ar[0].w);
        As[buf][a_c4 * 4 + 0][a_row1] = f2tf32(ar[1].x);
        As[buf][a_c4 * 4 + 1][a_row1] = f2tf32(ar[1].y);
        As[buf][a_c4 * 4 + 2][a_row1] = f2tf32(ar[1].z);
        As[buf][a_c4 * 4 + 3][a_row1] = f2tf32(ar[1].w);
        uint4 u0 = make_uint4(f2tf32(br[0].x), f2tf32(br[0].y),
                              f2tf32(br[0].z), f2tf32(br[0].w));
        uint4 u1 = make_uint4(f2tf32(br[1].x), f2tf32(br[1].y),
                              f2tf32(br[1].z), f2tf32(br[1].w));
        *(uint4*)&Bs[buf][b_r0][b_c4 * 4] = u0;
        *(uint4*)&Bs[buf][b_r1][b_c4 * 4] = u1;
    };

    #pragma unroll
    for (int mt = 0; mt < 4; mt++)
        #pragma unroll
        for (int nt = 0; nt < 4; nt++)
            #pragma unroll
            for (int i = 0; i < 4; i++) acc[mt][nt][i] = 0.0f;

    const int NKT = K / TBK;

    ldg(0);
    sts(0);
    __syncthreads();

    for (int kt = 0; kt < NKT; kt++) {
        int cur = kt & 1;
        if (kt + 1 < NKT) ldg((kt + 1) * TBK);

        #pragma unroll
        for (int ks = 0; ks < 2; ks++) {
            int k = ks * 8;
            uint32_t af[4][4], bf[4][2];
            #pragma unroll
            for (int mt = 0; mt < 4; mt++) {
                int rm = cx.wm + mt * 16;
                af[mt][0] = As[cur][k + cx.t][rm + cx.g];
                af[mt][1] = As[cur][k + cx.t][rm + cx.g + 8];
                af[mt][2] = As[cur][k + cx.t + 4][rm + cx.g];
                af[mt][3] = As[cur][k + cx.t + 4][rm + cx.g + 8];
            }
            #pragma unroll
            for (int nt = 0; nt < 4; nt++) {
                int cn = cx.wn + nt * 8;
                bf[nt][0] = Bs[cur][k + cx.t][cn + cx.g];
                bf[nt][1] = Bs[cur][k + cx.t + 4][cn + cx.g];
            }
            #pragma unroll
            for (int mt = 0; mt < 4; mt++)
                #pragma unroll
                for (int nt = 0; nt < 4; nt++)
                    MMA_TF32(acc[mt][nt], af[mt], bf[nt]);
        }

        if (kt + 1 < NKT) {
            sts(cur ^ 1);
            __syncthreads();
        }
    }
}

// ---------------------------------------------------------------------------
// Generic tf32 GEMM + bias (used for proj)
// ---------------------------------------------------------------------------
__global__ __launch_bounds__(256, 2)
void gemm_tf32_kernel(const float* __restrict__ A,
                      const float* __restrict__ Bm,
                      const float* __restrict__ bias,
                      float* __restrict__ C,
                      int M, int N, int K) {
    __shared__ uint32_t As[2][TBK][TBM + TPAD];
    __shared__ uint32_t Bs[2][TBK][TBN + TPAD];

    const int tid  = threadIdx.x;
    const int lane = tid & 31;
    const int warp = tid >> 5;
    GemmCtx cx;
    cx.wm = (warp & 1) * 64;
    cx.wn = (warp >> 1) * 32;
    cx.g = lane >> 2;
    cx.t = lane & 3;
    cx.m0 = blockIdx.y * TBM;
    cx.n0 = blockIdx.x * TBN;

    float acc[4][4][4];
    gemm_mainloop(A, Bm, M, N, K, cx, As, Bs, acc);

    #pragma unroll
    for (int nt = 0; nt < 4; nt++) {
        int gc = cx.n0 + cx.wn + nt * 8 + 2 * cx.t;
        float bia0 = bias[gc], bia1 = bias[gc + 1];
        #pragma unroll
        for (int mt = 0; mt < 4; mt++) {
            int r0 = cx.m0 + cx.wm + mt * 16 + cx.g;
            int r1 = r0 + 8;
            if (r0 < M) {
                float2 v = make_float2(acc[mt][nt][0] + bia0, acc[mt][nt][1] + bia1);
                *(float2*)(C + (size_t)r0 * N + gc) = v;
            }
            if (r1 < M) {
                float2 v = make_float2(acc[mt][nt][2] + bia0, acc[mt][nt][3] + bia1);
                *(float2*)(C + (size_t)r1 * N + gc) = v;
            }
        }
    }
}

// ---------------------------------------------------------------------------
// QKV GEMM + bias + fused RoPE + scatter into Q/K/V [b,h,s,64].
// Block's n-range (128 cols) lies entirely inside one of q/k/v (128 | 768).
// Thread holds column pairs (2t, 2t+1) == rope rotation pairs.
// ---------------------------------------------------------------------------
__global__ __launch_bounds__(256, 2)
void gemm_qkv_rope_kernel(const float* __restrict__ A,
                          const float* __restrict__ Bm,
                          const float* __restrict__ bias,
                          float* __restrict__ Q,
                          float* __restrict__ K_,
                          float* __restrict__ V) {
    __shared__ uint32_t As[2][TBK][TBM + TPAD];
    __shared__ uint32_t Bs[2][TBK][TBN + TPAD];

    const int tid  = threadIdx.x;
    const int lane = tid & 31;
    const int warp = tid >> 5;
    GemmCtx cx;
    cx.wm = (warp & 1) * 64;
    cx.wn = (warp >> 1) * 32;
    cx.g = lane >> 2;
    cx.t = lane & 3;
    cx.m0 = blockIdx.y * TBM;
    cx.n0 = blockIdx.x * TBN;

    const int M = B_ * S_;

    float acc[4][4][4];
    gemm_mainloop(A, Bm, M, QKV3_, E_, cx, As, Bs, acc);

    // Which of q/k/v this block's columns belong to
    const int sect = cx.n0 / E_;                 // 0=q 1=k 2=v
    float* dst = (sect == 0) ? Q : (sect == 1) ? K_ : V;
    const bool do_rope = (sect < 2);

    #pragma unroll
    for (int nt = 0; nt < 4; nt++) {
        int gc = cx.n0 + cx.wn + nt * 8 + 2 * cx.t;   // global col in [0,2304)
        int ec = gc - sect * E_;                      // col within [0,768)
        int h = ec >> 6;
        int d = ec & 63;                              // even
        float bia0 = bias[gc], bia1 = bias[gc + 1];

        #pragma unroll
        for (int mt = 0; mt < 4; mt++) {
            int r0 = cx.m0 + cx.wm + mt * 16 + cx.g;
            int r1 = r0 + 8;
            #pragma unroll
            for (int half = 0; half < 2; half++) {
                int r = half ? r1 : r0;
                if (r >= M) continue;
                float v0 = acc[mt][nt][half * 2 + 0] + bia0;
                float v1 = acc[mt][nt][half * 2 + 1] + bia1;
                int b = r / S_;
                int s = r - b * S_;
                if (do_rope && s > 0) {
                    int p = s - 1;
                    float cs = g_cos[p * DH_ + d];
                    float sn = g_sin[p * DH_ + d];
                    float n0 = v0 * cs - v1 * sn;
                    float n1 = v1 * cs + v0 * sn;
                    v0 = n0; v1 = n1;
                }
                size_t o = ((size_t)(b * H_ + h) * S_ + s) * DH_ + d;
                *(float2*)(dst + o) = make_float2(v0, v1);
            }
        }
    }
}

// ---------------------------------------------------------------------------
// TF32 tensor-core flash attention (unchanged from round 5).
// ---------------------------------------------------------------------------
#define FQ 64
#define FK 64
#define NTILES ((S_ + FK - 1) / FK)   // 10
#define PADA 68
#define PADV 72

__global__ __launch_bounds__(128, 1)
void flash_tf32_kernel(const float* __restrict__ Q,
                       const float* __restrict__ K,
                       const float* __restrict__ V,
                       const unsigned char* __restrict__ mask,
                       float* __restrict__ ctx) {
    int qb = blockIdx.x;
    int bh = blockIdx.y;
    int h = bh % H_, b = bh / H_;

    int tid  = threadIdx.x;
    int lane = tid & 31;
    int warp = tid >> 5;
    int g = lane >> 2;
    int t = lane & 3;
    int rm = warp * 16;

    __shared__ uint32_t Qs[FQ][PADA];
    __shared__ uint32_t Ks[FK][PADA];
    __shared__ uint32_t Vs[FK][PADV];
    __shared__ uint32_t Ps[FQ][PADA];
    __shared__ unsigned char ms[FK];

    const size_t bh_base = (size_t)bh * S_ * DH_;
    const int q0 = qb * FQ;

    #pragma unroll
    for (int i = 0; i < 8; i++) {
        int idx = tid + i * 128;
        int r = idx >> 4, c4 = idx & 15;
        float4 v = make_float4(0.f, 0.f, 0.f, 0.f);
        if (q0 + r < S_)
            v = *(const float4*)(Q + bh_base + (size_t)(q0 + r) * DH_ + c4 * 4);
        uint4 u = make_uint4(f2tf32(v.x), f2tf32(v.y), f2tf32(v.z), f2tf32(v.w));
        *(uint4*)&Qs[r][c4 * 4] = u;
    }

    float m_st[2] = {-1e30f, -1e30f};
    float l_st[2] = {0.0f, 0.0f};
    float O[8][4];
    #pragma unroll
    for (int nt = 0; nt < 8; nt++)
        #pragma unroll
        for (int i = 0; i < 4; i++) O[nt][i] = 0.0f;

    for (int kt = 0; kt < NTILES; kt++) {
        int k0 = kt * FK;
        __syncthreads();

        #pragma unroll
        for (int i = 0; i < 8; i++) {
            int idx = tid + i * 128;
            int r = idx >> 4, c4 = idx & 15;
            float4 kv = make_float4(0.f, 0.f, 0.f, 0.f);
            float4 vv = make_float4(0.f, 0.f, 0.f, 0.f);
            if (k0 + r < S_) {
                kv = *(const float4*)(K + bh_base + (size_t)(k0 + r) * DH_ + c4 * 4);
                vv = *(const float4*)(V + bh_base + (size_t)(k0 + r) * DH_ + c4 * 4);
            }
            uint4 ku = make_uint4(f2tf32(kv.x), f2tf32(kv.y), f2tf32(kv.z), f2tf32(kv.w));
            uint4 vu = make_uint4(f2tf32(vv.x), f2tf32(vv.y), f2tf32(vv.z), f2tf32(vv.w));
            *(uint4*)&Ks[r][c4 * 4] = ku;
            *(uint4*)&Vs[r][c4 * 4] = vu;
        }
        if (tid < FK)
            ms[tid] = (k0 + tid < S_) ? mask[b * S_ + k0 + tid] : (unsigned char)1;
        __syncthreads();

        float s[8][4];
        #pragma unroll
        for (int nt = 0; nt < 8; nt++)
            #pragma unroll
            for (int i = 0; i < 4; i++) s[nt][i] = 0.0f;

        #pragma unroll
        for (int ks = 0; ks < 8; ks++) {
            int kk = ks * 8;
            uint32_t af[4];
            af[0] = Qs[rm + g][kk + t];
            af[1] = Qs[rm + g + 8][kk + t];
            af[2] = Qs[rm + g][kk + t + 4];
            af[3] = Qs[rm + g + 8][kk + t + 4];
            #pragma unroll
            for (int nt = 0; nt < 8; nt++) {
                uint32_t bf[2];
                bf[0] = Ks[nt * 8 + g][kk + t];
                bf[1] = Ks[nt * 8 + g][kk + t + 4];
                MMA_TF32(s[nt], af, bf);
            }
        }

        #pragma unroll
        for (int nt = 0; nt < 8; nt++) {
            int c = nt * 8 + 2 * t;
            bool mk0 = ms[c], mk1 = ms[c + 1];
            s[nt][0] = mk0 ? -1e30f : s[nt][0] * 0.125f;
            s[nt][1] = mk1 ? -1e30f : s[nt][1] * 0.125f;
            s[nt][2] = mk0 ? -1e30f : s[nt][2] * 0.125f;
            s[nt][3] = mk1 ? -1e30f : s[nt][3] * 0.125f;
        }

        float tm0 = -1e30f, tm1 = -1e30f;
        #pragma unroll
        for (int nt = 0; nt < 8; nt++) {
            tm0 = fmaxf(tm0, fmaxf(s[nt][0], s[nt][1]));
            tm1 = fmaxf(tm1, fmaxf(s[nt][2], s[nt][3]));
        }
        tm0 = fmaxf(tm0, __shfl_xor_sync(0xffffffffu, tm0, 1));
        tm0 = fmaxf(tm0, __shfl_xor_sync(0xffffffffu, tm0, 2));
        tm1 = fmaxf(tm1, __shfl_xor_sync(0xffffffffu, tm1, 1));
        tm1 = fmaxf(tm1, __shfl_xor_sync(0xffffffffu, tm1, 2));

        float mn0 = fmaxf(m_st[0], tm0);
        float mn1 = fmaxf(m_st[1], tm1);
        float al0 = __expf(m_st[0] - mn0);
        float al1 = __expf(m_st[1] - mn1);

        float rs0 = 0.0f, rs1 = 0.0f;
        #pragma unroll
        for (int nt = 0; nt < 8; nt++) {
            float p0 = __expf(s[nt][0] - mn0);
            float p1 = __expf(s[nt][1] - mn0);
            float p2 = __expf(s[nt][2] - mn1);
            float p3 = __expf(s[nt][3] - mn1);
            s[nt][0] = p0; s[nt][1] = p1; s[nt][2] = p2; s[nt][3] = p3;
            rs0 += p0 + p1;
            rs1 += p2 + p3;
        }
        rs0 += __shfl_xor_sync(0xffffffffu, rs0, 1);
        rs0 += __shfl_xor_sync(0xffffffffu, rs0, 2);
        rs1 += __shfl_xor_sync(0xffffffffu, rs1, 1);
        rs1 += __shfl_xor_sync(0xffffffffu, rs1, 2);

        l_st[0] = l_st[0] * al0 + rs0;
        l_st[1] = l_st[1] * al1 + rs1;
        m_st[0] = mn0;
        m_st[1] = mn1;

        #pragma unroll
        for (int nt = 0; nt < 8; nt++) {
            O[nt][0] *= al0;
            O[nt][1] *= al0;
            O[nt][2] *= al1;
            O[nt][3] *= al1;
        }

        #pragma unroll
        for (int nt = 0; nt < 8; nt++) {
            int c = nt * 8 + 2 * t;
            *(uint2*)&Ps[rm + g][c]     = make_uint2(f2tf32(s[nt][0]), f2tf32(s[nt][1]));
            *(uint2*)&Ps[rm + g + 8][c] = make_uint2(f2tf32(s[nt][2]), f2tf32(s[nt][3]));
        }
        __syncwarp();

        #pragma unroll
        for (int ks = 0; ks < 8; ks++) {
            int kk = ks * 8;
            uint32_t af[4];
            af[0] = Ps[rm + g][kk + t];
            af[1] = Ps[rm + g + 8][kk + t];
            af[2] = Ps[rm + g][kk + t + 4];
            af[3] = Ps[rm + g + 8][kk + t + 4];
            #pragma unroll
            for (int nt = 0; nt < 8; nt++) {
                uint32_t bf[2];
                bf[0] = Vs[kk + t][nt * 8 + g];
                bf[1] = Vs[kk + t + 4][nt * 8 + g];
                MMA_TF32(O[nt], af, bf);
            }
        }
    }

    float inv0 = 1.0f / l_st[0];
    float inv1 = 1.0f / l_st[1];
    int r0 = q0 + rm + g;
    int r1 = r0 + 8;
    #pragma unroll
    for (int nt = 0; nt < 8; nt++) {
        int col = h * DH_ + nt * 8 + 2 * t;
        if (r0 < S_) {
            float2 v = make_float2(O[nt][0] * inv0, O[nt][1] * inv0);
            *(float2*)(ctx + (size_t)(b * S_ + r0) * E_ + col) = v;
        }
        if (r1 < S_) {
            float2 v = make_float2(O[nt][2] * inv1, O[nt][3] * inv1);
            *(float2*)(ctx + (size_t)(b * S_ + r1) * E_ + col) = v;
        }
    }
}

// ---------------------------------------------------------------------------
// Launch
// ---------------------------------------------------------------------------
extern "C" void kernel_launch(void* const* d_in, const int* in_sizes, int n_in,
                              void* d_out, int out_size) {
    const float* x      = (const float*)d_in[0];
    const unsigned char* mask = (const unsigned char*)d_in[1];
    const float* W_qkv  = (const float*)d_in[2];
    const float* b_qkv  = (const float*)d_in[3];
    const float* W_proj = (const float*)d_in[4];
    const float* b_proj = (const float*)d_in[5];
    float* out = (float*)d_out;

    float* ctx; cudaGetSymbolAddress((void**)&ctx, g_ctx);
    float* Qp;  cudaGetSymbolAddress((void**)&Qp, g_q);
    float* Kp;  cudaGetSymbolAddress((void**)&Kp, g_k);
    float* Vp;  cudaGetSymbolAddress((void**)&Vp, g_v);

    const int M = B_ * S_;   // 18464

    // 1) rope tables
    rope_build_kernel<<<NROT_, DH_>>>();

    // 2) qkv GEMM + bias + rope + scatter into Q/K/V [b,h,s,d]
    {
        dim3 grid(QKV3_ / TBN, (M + TBM - 1) / TBM);
        gemm_qkv_rope_kernel<<<grid, 256>>>(x, W_qkv, b_qkv, Qp, Kp, Vp);
    }

    // 3) flash attention (tf32 tensor cores)
    {
        dim3 grid(NTILES, BH_);
        flash_tf32_kernel<<<grid, 128>>>(Qp, Kp, Vp, mask, ctx);
    }

    // 4) out = ctx @ W_proj + b_proj  (tf32 tensor cores)
    {
        dim3 grid(E_ / TBN, (M + TBM - 1) / TBM);
        gemm_tf32_kernel<<<grid, 256>>>(ctx, W_proj, b_proj, out, M, E_, E_);
    }
}